// round 7
// baseline (speedup 1.0000x reference)
#include <cuda_runtime.h>
#include <cuda_bf16.h>

// Problem constants
#define CH   64
#define HW   1296
#define NTOT (CH * HW)   // 82944
#define LOG2E 1.4426950408889634f

#define SEGS 6            // j-segments per block
#define OPB  32           // outputs per block (= warp width)
#define J4   (HW / 4)     // 324 float4 per channel row
#define JSEG (J4 / SEGS)  // 54 float4 per segment

typedef unsigned long long u64;

// Scratch (device globals; float4 forces 16B alignment)
__device__ float4 g_q4 [NTOT / 4];
__device__ float4 g_k4 [NTOT / 4];   // k * log2e (SoA)
__device__ float4 g_v4 [NTOT / 4];   // v         (SoA)
__device__ float4 g_yp4[NTOT / 4];

__device__ __forceinline__ float ex2f(float x) {
    float r;
    asm("ex2.approx.f32 %0, %1;" : "=f"(r) : "f"(x));
    return r;
}
__device__ __forceinline__ u64 pack2(float lo, float hi) {
    u64 r; asm("mov.b64 %0, {%1, %2};" : "=l"(r) : "f"(lo), "f"(hi)); return r;
}
__device__ __forceinline__ void unpack2(float& lo, float& hi, u64 v) {
    asm("mov.b64 {%0, %1}, %2;" : "=f"(lo), "=f"(hi) : "l"(v));
}
__device__ __forceinline__ u64 mul2(u64 a, u64 b) {
    u64 r; asm("mul.rn.f32x2 %0, %1, %2;" : "=l"(r) : "l"(a), "l"(b)); return r;
}
__device__ __forceinline__ void adda2(u64& d, u64 a) {
    asm("add.rn.f32x2 %0, %1, %0;" : "+l"(d) : "l"(a));
}
__device__ __forceinline__ void fma2(u64& d, u64 a, u64 b) {
    asm("fma.rn.f32x2 %0, %1, %2, %0;" : "+l"(d) : "l"(a), "l"(b));
}

// ---------------------------------------------------------------------------
// Kernel A: 1x1-conv projections, pair-fused to halve L2 pixel traffic.
// pair 0: q & k from x (x loaded ONCE for both)
// pair 1: v & yp from y
// One thread = (pair, o, 4 pixels). 41472 threads = 324 blocks x 128.
// Per 4-c group: 2 weight LDG.128 (broadcast) + 4 pixel LDG.128 + 32 FFMA.
// L2 traffic: 2 x 64 x 331KB = 42MB (was 85MB) -> ~3.3us at 6300 B/cyc.
// ---------------------------------------------------------------------------
__global__ void proj_kernel(const float* __restrict__ x,
                            const float* __restrict__ y,
                            const float* __restrict__ Wq, const float* __restrict__ bq,
                            const float* __restrict__ Wk, const float* __restrict__ bk,
                            const float* __restrict__ Wv, const float* __restrict__ bv,
                            const float* __restrict__ Wp) {
    int g    = blockIdx.x * 128 + threadIdx.x;   // 0 .. 41471
    int pair = g / (NTOT / 4);                   // 0: q,k   1: v,yp
    int r    = g - pair * (NTOT / 4);
    int o    = r / (HW / 4);                     // out channel
    int i    = (r - o * (HW / 4)) * 4;           // pixel base

    const float* src;
    const float* W1;
    const float* W2;
    float b1, b2;
    if (pair == 0) { src = x; W1 = Wq; W2 = Wk; b1 = __ldg(&bq[o]); b2 = __ldg(&bk[o]); }
    else           { src = y; W1 = Wv; W2 = Wp; b1 = __ldg(&bv[o]); b2 = 0.0f; }

    float4 a1 = make_float4(b1, b1, b1, b1);
    float4 a2 = make_float4(b2, b2, b2, b2);
    const float4* W14 = reinterpret_cast<const float4*>(W1 + o * CH);
    const float4* W24 = reinterpret_cast<const float4*>(W2 + o * CH);

    #pragma unroll 4
    for (int cg = 0; cg < CH / 4; cg++) {
        float4 w1 = __ldg(&W14[cg]);
        float4 w2 = __ldg(&W24[cg]);
        const float* s0 = src + (cg * 4) * HW + i;
        float4 p0 = *reinterpret_cast<const float4*>(s0);
        float4 p1 = *reinterpret_cast<const float4*>(s0 + HW);
        float4 p2 = *reinterpret_cast<const float4*>(s0 + 2 * HW);
        float4 p3 = *reinterpret_cast<const float4*>(s0 + 3 * HW);

        a1.x = fmaf(w1.x, p0.x, a1.x); a1.y = fmaf(w1.x, p0.y, a1.y);
        a1.z = fmaf(w1.x, p0.z, a1.z); a1.w = fmaf(w1.x, p0.w, a1.w);
        a1.x = fmaf(w1.y, p1.x, a1.x); a1.y = fmaf(w1.y, p1.y, a1.y);
        a1.z = fmaf(w1.y, p1.z, a1.z); a1.w = fmaf(w1.y, p1.w, a1.w);
        a1.x = fmaf(w1.z, p2.x, a1.x); a1.y = fmaf(w1.z, p2.y, a1.y);
        a1.z = fmaf(w1.z, p2.z, a1.z); a1.w = fmaf(w1.z, p2.w, a1.w);
        a1.x = fmaf(w1.w, p3.x, a1.x); a1.y = fmaf(w1.w, p3.y, a1.y);
        a1.z = fmaf(w1.w, p3.z, a1.z); a1.w = fmaf(w1.w, p3.w, a1.w);

        a2.x = fmaf(w2.x, p0.x, a2.x); a2.y = fmaf(w2.x, p0.y, a2.y);
        a2.z = fmaf(w2.x, p0.z, a2.z); a2.w = fmaf(w2.x, p0.w, a2.w);
        a2.x = fmaf(w2.y, p1.x, a2.x); a2.y = fmaf(w2.y, p1.y, a2.y);
        a2.z = fmaf(w2.y, p1.z, a2.z); a2.w = fmaf(w2.y, p1.w, a2.w);
        a2.x = fmaf(w2.z, p2.x, a2.x); a2.y = fmaf(w2.z, p2.y, a2.y);
        a2.z = fmaf(w2.z, p2.z, a2.z); a2.w = fmaf(w2.z, p2.w, a2.w);
        a2.x = fmaf(w2.w, p3.x, a2.x); a2.y = fmaf(w2.w, p3.y, a2.y);
        a2.z = fmaf(w2.w, p3.z, a2.z); a2.w = fmaf(w2.w, p3.w, a2.w);
    }

    int idx4 = (o * HW + i) >> 2;
    if (pair == 0) {
        g_q4[idx4] = a1;
        g_k4[idx4] = make_float4(a2.x * LOG2E, a2.y * LOG2E,
                                 a2.z * LOG2E, a2.w * LOG2E);
    } else {
        g_v4[idx4]  = a1;
        g_yp4[idx4] = a2;
    }
}

// ---------------------------------------------------------------------------
// Kernel B: attention + gated residual.
// One block = one channel x 32 outputs x 6 j-segments (192 threads).
// k/v staged in smem (warp-uniform LDS.128 broadcast); f32x2 packed math
// trims the body to ~13 warp-instrs per 4 exps so the issue port (86.8%
// in R6) stops masking the MUFU floor.
// Shiftless softmax: |q.k| << 88 by construction; ratio is scale-invariant.
// ---------------------------------------------------------------------------
__global__ void attn_kernel(const float* __restrict__ gamma,
                            float* __restrict__ out) {
    __shared__ ulonglong2 ks2[J4];    // 4 packed k*log2e per entry
    __shared__ ulonglong2 vs2[J4];
    __shared__ float2 part[SEGS * OPB];

    int c  = blockIdx.y;
    int i0 = blockIdx.x * OPB;
    int t  = threadIdx.x;          // 0..191
    int il = t & 31;               // lane -> output
    int seg = t >> 5;              // warp -> j-segment (uniform per warp)

    // Stage channel's k/v rows into smem (coalesced 16B gmem loads)
    const ulonglong2* gk = reinterpret_cast<const ulonglong2*>(&g_k4[c * J4]);
    const ulonglong2* gv = reinterpret_cast<const ulonglong2*>(&g_v4[c * J4]);
    for (int idx = t; idx < J4; idx += SEGS * OPB) {
        ks2[idx] = gk[idx];
        vs2[idx] = gv[idx];
    }
    __syncthreads();

    int i = i0 + il;
    bool valid = (i < HW);
    float s = reinterpret_cast<const float*>(g_q4)[c * HW + (valid ? i : 0)];
    u64 s2 = pack2(s, s);

    int j0 = seg * JSEG;
    u64 d01 = 0, d23 = 0, n01 = 0, n23 = 0;   // bit pattern (0.f, 0.f)
    #pragma unroll 6
    for (int j = j0; j < j0 + JSEG; j++) {
        ulonglong2 kk = ks2[j];    // warp-uniform -> broadcast
        ulonglong2 vv = vs2[j];
        u64 a01 = mul2(kk.x, s2);
        u64 a23 = mul2(kk.y, s2);
        float f0, f1, f2, f3;
        unpack2(f0, f1, a01);
        unpack2(f2, f3, a23);
        u64 t01 = pack2(ex2f(f0), ex2f(f1));
        u64 t23 = pack2(ex2f(f2), ex2f(f3));
        adda2(d01, t01);
        adda2(d23, t23);
        fma2(n01, t01, vv.x);
        fma2(n23, t23, vv.y);
    }

    float a, b, e, f;
    unpack2(a, b, d01); unpack2(e, f, d23);
    float dsum = (a + b) + (e + f);
    unpack2(a, b, n01); unpack2(e, f, n23);
    float nsum = (a + b) + (e + f);

    part[t] = make_float2(dsum, nsum);
    __syncthreads();

    if (seg == 0 && valid) {
        float dd = 0.0f, nn = 0.0f;
        #pragma unroll
        for (int ss = 0; ss < SEGS; ss++) {
            float2 p = part[ss * OPB + il];
            dd += p.x; nn += p.y;
        }
        float gm = __ldg(&gamma[0]);
        float yp = reinterpret_cast<const float*>(g_yp4)[c * HW + i];
        out[c * HW + i] = (gm * (nn / dd) + yp) / (1.0f + gm);
    }
}

// ---------------------------------------------------------------------------
extern "C" void kernel_launch(void* const* d_in, const int* in_sizes, int n_in,
                              void* d_out, int out_size) {
    const float* x     = (const float*)d_in[0];
    const float* y     = (const float*)d_in[1];
    const float* Wq    = (const float*)d_in[2];
    const float* bq    = (const float*)d_in[3];
    const float* Wk    = (const float*)d_in[4];
    const float* bk    = (const float*)d_in[5];
    const float* Wv    = (const float*)d_in[6];
    const float* bv    = (const float*)d_in[7];
    const float* Wp    = (const float*)d_in[8];
    const float* gamma = (const float*)d_in[9];
    float* out = (float*)d_out;

    proj_kernel<<<(NTOT / 2) / 128, 128>>>(x, y, Wq, bq, Wk, bk, Wv, bv, Wp);

    dim3 grid((HW + OPB - 1) / OPB, CH);   // (41, 64)
    attn_kernel<<<grid, SEGS * OPB>>>(gamma, out);
}